// round 3
// baseline (speedup 1.0000x reference)
#include <cuda_runtime.h>
#include <cuda_bf16.h>

// Problem constants
#define B_ 8
#define T_ 2048
#define I_ 64
#define H_ 128
#define G3H 384                 // 3*H
#define TRI 2098176             // T*(T+1)/2
#define COUT_ELEMS (B_*T_*H_)   // 2097152

// Scratch (allocation-free rule: __device__ globals)
__device__ float g_xw[B_*T_*G3H];   // input projections (B,T,3H)
__device__ float g_h [B_*T_*H_];    // GRU hidden states
__device__ float g_e [B_*T_];       // attention logits
__device__ float g_w [B_*T_];       // exp(e - max)
__device__ float g_D [B_*T_];       // cumsum of w
__device__ float g_S [B_*16*H_];    // per-chunk partial sums for c_out scan

// ---------------------------------------------------------------------------
// f32x2 packed-FMA helpers (Blackwell; 2 fp32 FMAs per instruction per lane)
// ---------------------------------------------------------------------------
__device__ __forceinline__ void fma2(unsigned long long& acc,
                                     unsigned long long a,
                                     unsigned long long b) {
    asm("fma.rn.f32x2 %0, %1, %2, %0;" : "+l"(acc) : "l"(a), "l"(b));
}
__device__ __forceinline__ float pairsum(unsigned long long v) {
    float lo, hi;
    asm("mov.b64 {%0,%1}, %2;" : "=f"(lo), "=f"(hi) : "l"(v));
    return lo + hi;
}
__device__ __forceinline__ float sigmoidf_(float x) {
    return 1.0f / (1.0f + __expf(-x));
}

// ---------------------------------------------------------------------------
// 1) Input projection: xw[bt, j] = sum_k x[bt,k] * W_ih[j,k] + b_ih[j]
//    Block: 384 threads (one output row each, W row in regs), 64 bt per block.
// ---------------------------------------------------------------------------
__global__ __launch_bounds__(384, 1)
void proj_kernel(const float* __restrict__ x,
                 const float* __restrict__ W_ih,
                 const float* __restrict__ b_ih) {
    const int row = threadIdx.x;          // 0..383
    const int bt0 = blockIdx.x * 64;
    __shared__ __align__(16) float xs[64 * I_];

    unsigned long long w[32];             // 64 floats of W_ih row
    const unsigned long long* wr =
        reinterpret_cast<const unsigned long long*>(W_ih + row * I_);
#pragma unroll
    for (int k = 0; k < 32; k++) w[k] = wr[k];
    const float bi = b_ih[row];

    // cooperative load of 64 x-rows (64*64 floats = 1024 float4)
    const float4* xg = reinterpret_cast<const float4*>(x + (size_t)bt0 * I_);
    for (int i = threadIdx.x; i < 64 * I_ / 4; i += 384)
        reinterpret_cast<float4*>(xs)[i] = xg[i];
    __syncthreads();

    for (int j = 0; j < 64; j++) {
        unsigned long long a0 = 0ull, a1 = 0ull;
        const ulonglong2* hp = reinterpret_cast<const ulonglong2*>(xs + j * I_);
#pragma unroll
        for (int k = 0; k < 16; k++) {
            ulonglong2 hv = hp[k];
            fma2(a0, w[2 * k], hv.x);
            fma2(a1, w[2 * k + 1], hv.y);
        }
        g_xw[(size_t)(bt0 + j) * G3H + row] = pairsum(a0) + pairsum(a1) + bi;
    }
}

// ---------------------------------------------------------------------------
// 2) GRU recurrence. One CTA per batch, 384 threads, W_hh row in registers.
//    Per step: 384 dots of length 128 (f32x2), gates, 2 barriers.
// ---------------------------------------------------------------------------
__global__ __launch_bounds__(384, 1)
void gru_kernel(const float* __restrict__ W_hh,
                const float* __restrict__ b_hh) {
    const int b = blockIdx.x;
    const int row = threadIdx.x;          // 0..383 (r: 0-127, z: 128-255, n: 256-383)
    __shared__ __align__(16) float h_sh[H_];
    __shared__ float r_sh[H_];
    __shared__ float z_sh[H_];

    unsigned long long w[64];             // 128 floats of W_hh row
    const unsigned long long* wr =
        reinterpret_cast<const unsigned long long*>(W_hh + row * H_);
#pragma unroll
    for (int k = 0; k < 64; k++) w[k] = wr[k];
    const float bh = b_hh[row];

    if (row < H_) h_sh[row] = 0.0f;
    float h_reg = 0.0f;                   // n-threads own h[row-256]

    const float* xwb = g_xw + (size_t)b * T_ * G3H;
    float xval_next = __ldg(xwb + row);   // prefetch t=0
    __syncthreads();

    for (int t = 0; t < T_; t++) {
        const float xval = xval_next;
        if (t < T_ - 1) xval_next = __ldg(xwb + (size_t)(t + 1) * G3H + row);

        unsigned long long a0 = 0ull, a1 = 0ull;
        const ulonglong2* hp = reinterpret_cast<const ulonglong2*>(h_sh);
#pragma unroll
        for (int k = 0; k < 32; k++) {
            ulonglong2 hv = hp[k];        // broadcast read, conflict-free
            fma2(a0, w[2 * k], hv.x);
            fma2(a1, w[2 * k + 1], hv.y);
        }
        const float dot = pairsum(a0) + pairsum(a1) + bh;   // hw + b_hh

        if (row < H_) {
            r_sh[row] = sigmoidf_(xval + dot);
        } else if (row < 2 * H_) {
            z_sh[row - H_] = sigmoidf_(xval + dot);
        }
        __syncthreads();   // r,z ready; all h_sh reads done

        if (row >= 2 * H_) {
            const int i = row - 2 * H_;
            const float n = tanhf(fmaf(r_sh[i], dot, xval));
            const float z = z_sh[i];
            const float hn = (1.0f - z) * n + z * h_reg;
            h_reg = hn;
            h_sh[i] = hn;
            g_h[((size_t)b * T_ + t) * H_ + i] = hn;
        }
        __syncthreads();   // h_sh updated before next step's dots
    }
}

// ---------------------------------------------------------------------------
// 3) e[bt] = dot(h[bt,:], W_lin) + b_lin   (one warp per bt)
// ---------------------------------------------------------------------------
__global__ __launch_bounds__(128)
void e_kernel(const float* __restrict__ W_lin,
              const float* __restrict__ b_lin) {
    const int bt = blockIdx.x * 4 + (threadIdx.x >> 5);
    const int lane = threadIdx.x & 31;
    float4 hv = reinterpret_cast<const float4*>(g_h + (size_t)bt * H_)[lane];
    float4 wv = reinterpret_cast<const float4*>(W_lin)[lane];
    float s = hv.x * wv.x + hv.y * wv.y + hv.z * wv.z + hv.w * wv.w;
#pragma unroll
    for (int o = 16; o; o >>= 1) s += __shfl_xor_sync(0xffffffffu, s, o);
    if (lane == 0) g_e[bt] = s + b_lin[0];
}

// ---------------------------------------------------------------------------
// 4) Per batch: M = max(e), w = exp(e-M), D = inclusive cumsum(w)
// ---------------------------------------------------------------------------
__global__ __launch_bounds__(512, 1)
void scan_kernel() {
    const int b = blockIdx.x;
    const int tid = threadIdx.x;
    __shared__ float sh[512];

    const float* eb = g_e + b * T_;
    float4 ev = reinterpret_cast<const float4*>(eb)[tid];

    float m = fmaxf(fmaxf(ev.x, ev.y), fmaxf(ev.z, ev.w));
    sh[tid] = m;
    __syncthreads();
#pragma unroll
    for (int o = 256; o; o >>= 1) {
        if (tid < o) sh[tid] = fmaxf(sh[tid], sh[tid + o]);
        __syncthreads();
    }
    const float M = sh[0];
    __syncthreads();

    const float w0 = __expf(ev.x - M);
    const float w1 = __expf(ev.y - M);
    const float w2 = __expf(ev.z - M);
    const float w3 = __expf(ev.w - M);
    const float p0 = w0, p1 = p0 + w1, p2 = p1 + w2, p3 = p2 + w3;

    sh[tid] = p3;
    __syncthreads();
    for (int o = 1; o < 512; o <<= 1) {     // Hillis-Steele inclusive scan
        float v = (tid >= o) ? sh[tid - o] : 0.0f;
        __syncthreads();
        sh[tid] += v;
        __syncthreads();
    }
    const float base = sh[tid] - p3;        // exclusive prefix of this thread

    reinterpret_cast<float4*>(g_w + b * T_)[tid] = make_float4(w0, w1, w2, w3);
    reinterpret_cast<float4*>(g_D + b * T_)[tid] =
        make_float4(base + p0, base + p1, base + p2, base + p3);
}

// ---------------------------------------------------------------------------
// 5) c_out prefix scan, 2-pass chunked (16 chunks of 128 steps per batch)
// ---------------------------------------------------------------------------
__global__ __launch_bounds__(128)
void cout_partial_kernel() {
    const int c = blockIdx.x, b = blockIdx.y, tid = threadIdx.x;
    const float* wb = g_w + b * T_;
    float acc = 0.0f;
    for (int t = c * 128; t < c * 128 + 128; t++)
        acc = fmaf(__ldg(wb + t), __ldg(&g_h[((size_t)b * T_ + t) * H_ + tid]), acc);
    g_S[(b * 16 + c) * H_ + tid] = acc;
}

__global__ __launch_bounds__(128)
void cout_main_kernel(float* __restrict__ out) {
    const int c = blockIdx.x, b = blockIdx.y, tid = threadIdx.x;
    float acc = 0.0f;
    for (int c2 = 0; c2 < c; c2++) acc += g_S[(b * 16 + c2) * H_ + tid];
    const float* wb = g_w + b * T_;
    const float* Db = g_D + b * T_;
    for (int t = c * 128; t < c * 128 + 128; t++) {
        acc = fmaf(__ldg(wb + t), __ldg(&g_h[((size_t)b * T_ + t) * H_ + tid]), acc);
        out[((size_t)b * T_ + t) * H_ + tid] = acc * (1.0f / __ldg(Db + t));
    }
}

// ---------------------------------------------------------------------------
// 6) alpha_out[b, t(t+1)/2 + s] = w[b,s] / D[b,t],  s = 0..t
// ---------------------------------------------------------------------------
__global__ __launch_bounds__(256)
void alpha_kernel(float* __restrict__ out) {
    const int t = blockIdx.x, b = blockIdx.y;
    const float invD = 1.0f / g_D[b * T_ + t];
    const float* wb = g_w + b * T_;
    float* dst = out + COUT_ELEMS + (size_t)b * TRI + ((size_t)t * (t + 1)) / 2;
    for (int s = threadIdx.x; s <= t; s += 256)
        dst[s] = wb[s] * invD;
}

// ---------------------------------------------------------------------------
extern "C" void kernel_launch(void* const* d_in, const int* in_sizes, int n_in,
                              void* d_out, int out_size) {
    const float* x     = (const float*)d_in[0];
    const float* W_ih  = (const float*)d_in[1];
    const float* W_hh  = (const float*)d_in[2];
    const float* b_ih  = (const float*)d_in[3];
    const float* b_hh  = (const float*)d_in[4];
    const float* W_lin = (const float*)d_in[5];
    const float* b_lin = (const float*)d_in[6];
    float* out = (float*)d_out;

    proj_kernel<<<256, 384>>>(x, W_ih, b_ih);
    gru_kernel<<<B_, 384>>>(W_hh, b_hh);
    e_kernel<<<(B_ * T_) / 4, 128>>>(W_lin, b_lin);
    scan_kernel<<<B_, 512>>>();
    cout_partial_kernel<<<dim3(16, B_), 128>>>();
    cout_main_kernel<<<dim3(16, B_), 128>>>(out);
    alpha_kernel<<<dim3(T_, B_), 256>>>(out);
}